// round 10
// baseline (speedup 1.0000x reference)
#include <cuda_runtime.h>

#define HEADS 4
#define NEG_SLOPE 0.2f

static const int N_CAP  = 100000;
static const int EN_CAP = 1700000;
static const int SCAN_CHUNK = 512;
static const int NBKT = 1024;

// ---------------- scratch (static device globals; no allocation) -------------
__device__ float g_h  [N_CAP * 64];   // transformed features h = in @ W   [N, F]
__device__ float g_o  [N_CAP * 64];   // aggregated output (next layer in) [N, F]
__device__ float g_als[N_CAP * HEADS];
__device__ float g_ald[N_CAP * HEADS];
__device__ int   g_src[EN_CAP];
__device__ int   g_dst[EN_CAP];
__device__ int   g_csr_src[EN_CAP];
__device__ int   g_deg[N_CAP];
__device__ int   g_inc[N_CAP];
__device__ int   g_off[N_CAP + 1];
__device__ int   g_cursor[N_CAP];
__device__ int   g_bsum[256];
__device__ int   g_boff[256];
__device__ int   g_bcnt[NBKT];        // degree-bucket histogram
__device__ int   g_bcur[NBKT];
__device__ int   g_boff2[NBKT];
__device__ int   g_perm[N_CAP];       // nodes sorted by degree (agg order)
__device__ float g_psum[64 * 8];
__device__ float g_pcnt[64];
__device__ int   g_is64;

// ---------------- helpers ----------------------------------------------------
__device__ __forceinline__ float lrelu(float x) { return x > 0.f ? x : NEG_SLOPE * x; }

// ---------------- index-width detection --------------------------------------
__global__ void k_detect(const unsigned* __restrict__ w, int pairs) {
    __shared__ int any;
    if (threadIdx.x == 0) any = 0;
    __syncthreads();
    int lim = pairs < 4096 ? pairs : 4096;
    int local = 0;
    for (int i = threadIdx.x; i < lim; i += blockDim.x)
        if (w[2 * i + 1] != 0u) local = 1;
    if (local) atomicExch(&any, 1);
    __syncthreads();
    if (threadIdx.x == 0) g_is64 = (any == 0) ? 1 : 0;
}

// ---------------- zero transient state ---------------------------------------
__global__ void k_zero(int N) {
    int i = blockIdx.x * blockDim.x + threadIdx.x;
    if (i < N) { g_deg[i] = 0; g_cursor[i] = 0; }
    if (i < NBKT) { g_bcnt[i] = 0; g_bcur[i] = 0; }
    if (i < 512) g_psum[i] = 0.f;
    if (i < 64)  g_pcnt[i] = 0.f;
}

// ---------------- decode edges + dst histogram --------------------------------
__global__ void k_hist(const void* __restrict__ ei, int E, int N) {
    int i = blockIdx.x * blockDim.x + threadIdx.x;
    int EN = E + N;
    if (i >= EN) return;
    int s, d;
    if (i < E) {
        if (g_is64) {
            const long long* p = (const long long*)ei;
            s = (int)p[i]; d = (int)p[E + i];
        } else {
            const int* p = (const int*)ei;
            s = p[i]; d = p[E + i];
        }
    } else {             // self-loops appended (PyG GATConv behavior)
        s = d = i - E;
    }
    g_src[i] = s;
    g_dst[i] = d;
    atomicAdd(&g_deg[d], 1);
}

// ---------------- 3-phase exclusive scan of g_deg -> g_off --------------------
__global__ __launch_bounds__(SCAN_CHUNK) void k_scanA(int N) {
    __shared__ int sh[SCAN_CHUNK];
    int i = blockIdx.x * SCAN_CHUNK + threadIdx.x;
    int v = (i < N) ? g_deg[i] : 0;
    sh[threadIdx.x] = v;
    __syncthreads();
    for (int off = 1; off < SCAN_CHUNK; off <<= 1) {
        int t = (threadIdx.x >= off) ? sh[threadIdx.x - off] : 0;
        __syncthreads();
        sh[threadIdx.x] += t;
        __syncthreads();
    }
    if (i < N) g_inc[i] = sh[threadIdx.x];
    if (threadIdx.x == SCAN_CHUNK - 1) g_bsum[blockIdx.x] = sh[SCAN_CHUNK - 1];
}

__global__ __launch_bounds__(256) void k_scanB(int NB) {
    __shared__ int sh[256];
    int t = threadIdx.x;
    int v = (t < NB) ? g_bsum[t] : 0;
    sh[t] = v;
    __syncthreads();
    for (int off = 1; off < 256; off <<= 1) {
        int tv = (t >= off) ? sh[t - off] : 0;
        __syncthreads();
        sh[t] += tv;
        __syncthreads();
    }
    if (t < NB) g_boff[t] = sh[t] - v;   // exclusive
}

__global__ void k_scanC(int N) {
    int i = blockIdx.x * blockDim.x + threadIdx.x;
    if (i >= N) return;
    int b = i / SCAN_CHUNK;
    int inc = g_inc[i] + g_boff[b];
    g_off[i] = inc - g_deg[i];
    if (i == N - 1) g_off[N] = inc;
}

// ---------------- scatter edges into CSR order --------------------------------
__global__ void k_csr_scatter(int EN) {
    int i = blockIdx.x * blockDim.x + threadIdx.x;
    if (i >= EN) return;
    int d = g_dst[i];
    int pos = g_off[d] + atomicAdd(&g_cursor[d], 1);
    g_csr_src[pos] = g_src[i];
}

// ---------------- degree-bucket counting sort -> g_perm -----------------------
// Nodes sorted (ascending, bucketed) by in-degree so warp-co-resident nodes in
// k_agg have near-equal trip counts (kills the max-of-degrees divergence).
__global__ void k_bhist(int N) {
    int i = blockIdx.x * blockDim.x + threadIdx.x;
    if (i >= N) return;
    int b = min(g_deg[i], NBKT - 1);
    atomicAdd(&g_bcnt[b], 1);
}

__global__ __launch_bounds__(NBKT) void k_bscan() {
    __shared__ int sh[NBKT];
    int t = threadIdx.x;
    int v = g_bcnt[t];
    sh[t] = v;
    __syncthreads();
    for (int off = 1; off < NBKT; off <<= 1) {
        int tv = (t >= off) ? sh[t - off] : 0;
        __syncthreads();
        sh[t] += tv;
        __syncthreads();
    }
    g_boff2[t] = sh[t] - v;   // exclusive
}

__global__ void k_bperm(int N) {
    int i = blockIdx.x * blockDim.x + threadIdx.x;
    if (i >= N) return;
    int b = min(g_deg[i], NBKT - 1);
    int pos = g_boff2[b] + atomicAdd(&g_bcur[b], 1);
    g_perm[pos] = i;
}

// ---------------- GEMM + fused attention-logit epilogue ----------------------
// g_h = act(in [+bias]) @ W ; g_als/g_ald = per-head dot(h_row, a_src/a_dst).
// W row slice read as one LDS.128 (contiguous, 16B-aligned) — halves smem
// crossbar pressure vs 4 scalar LDS.
template<int K, int M, int ROWS>
__global__ __launch_bounds__(256) void k_gemm(
    const float* __restrict__ in_ext, int use_int,
    const float* __restrict__ W, const float* __restrict__ bias,
    const float* __restrict__ a_src, const float* __restrict__ a_dst, int N)
{
    constexpr int CG  = M / 4;
    constexpr int RG  = 256 / CG;
    constexpr int RPT = ROWS / RG;
    constexpr int OC  = M / HEADS;
    constexpr int RED = (OC >= 4) ? OC / 4 : 1;
    constexpr int KP  = (K == 128) ? K : (K + 1);
    __shared__ __align__(16) float sW[K * M];
    __shared__ float sIn[ROWS * KP];

    const float* in = use_int ? g_o : in_ext;
    int r0 = blockIdx.x * ROWS;

    for (int i = threadIdx.x; i < K * M; i += 256) sW[i] = W[i];
    for (int i = threadIdx.x; i < ROWS * K; i += 256) {
        int r = i / K, k = i - r * K;
        int gr = r0 + r;
        float v = 0.f;
        if (gr < N) {
            v = in[gr * K + k];
            if (bias) { v += bias[k]; v = fmaxf(v, 0.f); }
        }
        sIn[r * KP + k] = v;
    }
    __syncthreads();

    int cg = threadIdx.x % CG;
    int rg = threadIdx.x / CG;
    float acc[RPT][4];
#pragma unroll
    for (int i = 0; i < RPT; i++)
        acc[i][0] = acc[i][1] = acc[i][2] = acc[i][3] = 0.f;

#pragma unroll 8
    for (int k = 0; k < K; k++) {
        float4 w = *(const float4*)&sW[k * M + cg * 4];
#pragma unroll
        for (int i = 0; i < RPT; i++) {
            float a = sIn[(rg * RPT + i) * KP + k];
            acc[i][0] += a * w.x; acc[i][1] += a * w.y;
            acc[i][2] += a * w.z; acc[i][3] += a * w.w;
        }
    }

    float4 asv = *(const float4*)&a_src[cg * 4];
    float4 adv = *(const float4*)&a_dst[cg * 4];

#pragma unroll
    for (int i = 0; i < RPT; i++) {
        int gr = r0 + rg * RPT + i;
        bool ok = (gr < N);
        if (ok) {
            float4 v = make_float4(acc[i][0], acc[i][1], acc[i][2], acc[i][3]);
            *(float4*)&g_h[gr * M + cg * 4] = v;
        }
        if constexpr (OC >= 4) {
            float vs = acc[i][0]*asv.x + acc[i][1]*asv.y + acc[i][2]*asv.z + acc[i][3]*asv.w;
            float vd = acc[i][0]*adv.x + acc[i][1]*adv.y + acc[i][2]*adv.z + acc[i][3]*adv.w;
#pragma unroll
            for (int o = 1; o < RED; o <<= 1) {
                vs += __shfl_xor_sync(0xffffffffu, vs, o, 32);
                vd += __shfl_xor_sync(0xffffffffu, vd, o, 32);
            }
            if (ok && (cg % RED) == 0) {
                int head = cg / RED;
                g_als[gr * HEADS + head] = vs;
                g_ald[gr * HEADS + head] = vd;
            }
        } else {  // OC == 2: thread's 4 cols span 2 heads
            float vs0 = acc[i][0]*asv.x + acc[i][1]*asv.y;
            float vd0 = acc[i][0]*adv.x + acc[i][1]*adv.y;
            float vs1 = acc[i][2]*asv.z + acc[i][3]*asv.w;
            float vd1 = acc[i][2]*adv.z + acc[i][3]*adv.w;
            if (ok) {
                g_als[gr * HEADS + cg * 2 + 0] = vs0;
                g_ald[gr * HEADS + cg * 2 + 0] = vd0;
                g_als[gr * HEADS + cg * 2 + 1] = vs1;
                g_ald[gr * HEADS + cg * 2 + 1] = vd1;
            }
        }
    }
}

// ---------------- fused softmax + aggregation (round-6 core + degree sort) ----
// TPN = F/V threads per node; nodes assigned via g_perm (degree-sorted) so all
// nodes sharing a warp walk near-equal edge counts. 8-edge batches preload
// indices and logits; feature float4 consumed immediately (register-lean).
// Softmax shift skipped (shift-invariant, O(1) logits).
template<int OC>
__global__ __launch_bounds__(256) void k_agg(int N) {
    constexpr int F   = HEADS * OC;
    constexpr int V   = (OC >= 4) ? 4 : 2;
    constexpr int TPN = F / V;
    constexpr int LPH = OC / V;        // lanes per head
    constexpr int NPB = 256 / TPN;
    int raw = blockIdx.x * NPB + threadIdx.x / TPN;
    if (raw >= N) raw = N - 1;         // clamp: duplicate compute, identical writes
    int node = g_perm[raw];
    int t    = threadIdx.x % TPN;
    int head = t / LPH;

    int beg = g_off[node], end = g_off[node + 1];
    float ald_d = g_ald[node * HEADS + head];

    float acc[V];
#pragma unroll
    for (int v = 0; v < V; v++) acc[v] = 0.f;
    float ssum = 0.f;

    int p = beg;
    for (; p + 8 <= end; p += 8) {
        int ss[8];
#pragma unroll
        for (int j = 0; j < 8; j++) ss[j] = g_csr_src[p + j];
        float al[8];
#pragma unroll
        for (int j = 0; j < 8; j++) al[j] = g_als[ss[j] * HEADS + head];
#pragma unroll
        for (int j = 0; j < 8; j++) {
            float ex = __expf(lrelu(al[j] + ald_d));
            ssum += ex;
            const float* hp = &g_h[ss[j] * F + t * V];
            if constexpr (V == 4) {
                float4 hv = *(const float4*)hp;
                acc[0] += ex * hv.x; acc[1] += ex * hv.y;
                acc[2] += ex * hv.z; acc[3] += ex * hv.w;
            } else {
                float2 hv = *(const float2*)hp;
                acc[0] += ex * hv.x; acc[1] += ex * hv.y;
            }
        }
    }
    for (; p < end; p++) {
        int s = g_csr_src[p];
        float ex = __expf(lrelu(g_als[s * HEADS + head] + ald_d));
        ssum += ex;
        const float* hp = &g_h[s * F + t * V];
        if constexpr (V == 4) {
            float4 hv = *(const float4*)hp;
            acc[0] += ex * hv.x; acc[1] += ex * hv.y;
            acc[2] += ex * hv.z; acc[3] += ex * hv.w;
        } else {
            float2 hv = *(const float2*)hp;
            acc[0] += ex * hv.x; acc[1] += ex * hv.y;
        }
    }

    float inv = 1.f / (ssum + 1e-16f);
    float* op = &g_o[node * F + t * V];
    if constexpr (V == 4)
        *(float4*)op = make_float4(acc[0] * inv, acc[1] * inv, acc[2] * inv, acc[3] * inv);
    else
        *(float2*)op = make_float2(acc[0] * inv, acc[1] * inv);
}

// ---------------- pooling + fc -----------------------------------------------
__global__ void k_pool(const void* __restrict__ batch,
                       const float* __restrict__ b4, int N) {
    int n = blockIdx.x * blockDim.x + threadIdx.x;
    if (n >= N) return;
    int g = g_is64 ? (int)((const long long*)batch)[n]
                   : ((const int*)batch)[n];
#pragma unroll
    for (int j = 0; j < 8; j++) {
        float v = fmaxf(g_o[n * 8 + j] + b4[j], 0.f);
        atomicAdd(&g_psum[g * 8 + j], v);
    }
    atomicAdd(&g_pcnt[g], 1.f);
}

__global__ void k_fc(const float* __restrict__ Wfc,
                     const float* __restrict__ bfc, float* __restrict__ out) {
    int b = blockIdx.x, o = threadIdx.x;  // grid 64, block 32
    float c = fmaxf(g_pcnt[b], 1.f);
    float acc = bfc[o];
#pragma unroll
    for (int j = 0; j < 8; j++)
        acc += (g_psum[b * 8 + j] / c) * Wfc[j * 32 + o];
    out[b * 32 + o] = acc;
}

// ---------------- launch ------------------------------------------------------
extern "C" void kernel_launch(void* const* d_in, const int* in_sizes, int n_in,
                              void* d_out, int out_size) {
    const float* x    = (const float*)d_in[0];
    const void*  ei   = d_in[1];
    const void*  batch= d_in[2];
    const float* W1  = (const float*)d_in[3];
    const float* as1 = (const float*)d_in[4];
    const float* ad1 = (const float*)d_in[5];
    const float* b1  = (const float*)d_in[6];
    const float* W2  = (const float*)d_in[7];
    const float* as2 = (const float*)d_in[8];
    const float* ad2 = (const float*)d_in[9];
    const float* b2  = (const float*)d_in[10];
    const float* W3  = (const float*)d_in[11];
    const float* as3 = (const float*)d_in[12];
    const float* ad3 = (const float*)d_in[13];
    const float* b3  = (const float*)d_in[14];
    const float* W4  = (const float*)d_in[15];
    const float* as4 = (const float*)d_in[16];
    const float* ad4 = (const float*)d_in[17];
    const float* b4  = (const float*)d_in[18];
    const float* Wfc = (const float*)d_in[19];
    const float* bfc = (const float*)d_in[20];
    float* out = (float*)d_out;

    int N  = in_sizes[0] / 128;
    int E  = in_sizes[1] / 2;
    int EN = E + N;

    int nb = (N + 255) / 256;
    int eb = (EN + 255) / 256;
    int NB = (N + SCAN_CHUNK - 1) / SCAN_CHUNK;

    // Side stream + fork/join events, created once on the FIRST call (the
    // correctness run, which is NOT captured) — nothing created inside the
    // graph, no device memory allocated.
    static cudaStream_t s2 = nullptr;
    static cudaEvent_t evFork = nullptr, evJoin = nullptr;
    if (s2 == nullptr) {
        cudaStreamCreateWithFlags(&s2, cudaStreamNonBlocking);
        cudaEventCreateWithFlags(&evFork, cudaEventDisableTiming);
        cudaEventCreateWithFlags(&evJoin, cudaEventDisableTiming);
    }

    // ---- fork: CSR + degree-sort build on s2, GEMM1 on the main stream ----
    cudaEventRecord(evFork, 0);
    cudaStreamWaitEvent(s2, evFork, 0);

    k_detect<<<1, 256, 0, s2>>>((const unsigned*)ei, E);
    k_zero<<<nb, 256, 0, s2>>>(N);
    k_hist<<<eb, 256, 0, s2>>>(ei, E, N);
    k_scanA<<<NB, SCAN_CHUNK, 0, s2>>>(N);
    k_scanB<<<1, 256, 0, s2>>>(NB);
    k_scanC<<<nb, 256, 0, s2>>>(N);
    k_csr_scatter<<<eb, 256, 0, s2>>>(EN);
    k_bhist<<<nb, 256, 0, s2>>>(N);
    k_bscan<<<1, NBKT, 0, s2>>>();
    k_bperm<<<nb, 256, 0, s2>>>(N);

    // layer-1 GEMM runs concurrently on the main stream (depends only on x/W1)
    k_gemm<128, 64, 32><<<(N + 31) / 32, 256>>>(x, 0, W1, nullptr, as1, ad1, N);

    // ---- join: aggregation needs CSR + perm + GEMM1 results ----
    cudaEventRecord(evJoin, s2);
    cudaStreamWaitEvent(0, evJoin, 0);

    // ---- layer 1 (F = 64) ----
    k_agg<16><<<(N + 15) / 16, 256>>>(N);

    // ---- layer 2 (in = relu(g_o + b1)), F = 32 ----
    k_gemm<64, 32, 128><<<(N + 127) / 128, 256>>>(nullptr, 1, W2, b1, as2, ad2, N);
    k_agg<8><<<(N + 31) / 32, 256>>>(N);

    // ---- layer 3, F = 16 ----
    k_gemm<32, 16, 256><<<(N + 255) / 256, 256>>>(nullptr, 1, W3, b2, as3, ad3, N);
    k_agg<4><<<(N + 63) / 64, 256>>>(N);

    // ---- layer 4, F = 8 ----
    k_gemm<16, 8, 512><<<(N + 511) / 512, 256>>>(nullptr, 1, W4, b3, as4, ad4, N);
    k_agg<2><<<(N + 63) / 64, 256>>>(N);

    // ---- global mean pool (relu(g_o + b4)) + fc ----
    k_pool<<<nb, 256>>>(batch, b4, N);
    k_fc<<<64, 32>>>(Wfc, bfc, out);
}

// round 11
// speedup vs baseline: 1.0192x; 1.0192x over previous
#include <cuda_runtime.h>

#define HEADS 4
#define NEG_SLOPE 0.2f

static const int N_CAP  = 100000;
static const int EN_CAP = 1700000;
static const int SCAN_CHUNK = 512;

// ---------------- scratch (static device globals; no allocation) -------------
__device__ float g_h  [N_CAP * 64];   // transformed features h = in @ W   [N, F]
__device__ float g_o  [N_CAP * 64];   // aggregated output (next layer in) [N, F]
__device__ float g_als[N_CAP * HEADS];
__device__ float g_ald[N_CAP * HEADS];
__device__ int   g_src[EN_CAP];
__device__ int   g_dst[EN_CAP];
__device__ int   g_csr_src[EN_CAP];
__device__ int   g_deg[N_CAP];
__device__ int   g_inc[N_CAP];
__device__ int   g_off[N_CAP + 1];
__device__ int   g_cursor[N_CAP];
__device__ int   g_bsum[256];
__device__ int   g_boff[256];
__device__ float g_psum[64 * 8];
__device__ float g_pcnt[64];
__device__ int   g_is64;

// ---------------- helpers ----------------------------------------------------
__device__ __forceinline__ float lrelu(float x) { return x > 0.f ? x : NEG_SLOPE * x; }

// ---------------- index-width detection --------------------------------------
__global__ void k_detect(const unsigned* __restrict__ w, int pairs) {
    __shared__ int any;
    if (threadIdx.x == 0) any = 0;
    __syncthreads();
    int lim = pairs < 4096 ? pairs : 4096;
    int local = 0;
    for (int i = threadIdx.x; i < lim; i += blockDim.x)
        if (w[2 * i + 1] != 0u) local = 1;
    if (local) atomicExch(&any, 1);
    __syncthreads();
    if (threadIdx.x == 0) g_is64 = (any == 0) ? 1 : 0;
}

// ---------------- zero transient state ---------------------------------------
__global__ void k_zero(int N) {
    int i = blockIdx.x * blockDim.x + threadIdx.x;
    if (i < N) { g_deg[i] = 0; g_cursor[i] = 0; }
    if (i < 512) g_psum[i] = 0.f;
    if (i < 64)  g_pcnt[i] = 0.f;
}

// ---------------- decode edges + dst histogram --------------------------------
__global__ void k_hist(const void* __restrict__ ei, int E, int N) {
    int i = blockIdx.x * blockDim.x + threadIdx.x;
    int EN = E + N;
    if (i >= EN) return;
    int s, d;
    if (i < E) {
        if (g_is64) {
            const long long* p = (const long long*)ei;
            s = (int)p[i]; d = (int)p[E + i];
        } else {
            const int* p = (const int*)ei;
            s = p[i]; d = p[E + i];
        }
    } else {             // self-loops appended (PyG GATConv behavior)
        s = d = i - E;
    }
    g_src[i] = s;
    g_dst[i] = d;
    atomicAdd(&g_deg[d], 1);
}

// ---------------- 3-phase exclusive scan of g_deg -> g_off --------------------
__global__ __launch_bounds__(SCAN_CHUNK) void k_scanA(int N) {
    __shared__ int sh[SCAN_CHUNK];
    int i = blockIdx.x * SCAN_CHUNK + threadIdx.x;
    int v = (i < N) ? g_deg[i] : 0;
    sh[threadIdx.x] = v;
    __syncthreads();
    for (int off = 1; off < SCAN_CHUNK; off <<= 1) {
        int t = (threadIdx.x >= off) ? sh[threadIdx.x - off] : 0;
        __syncthreads();
        sh[threadIdx.x] += t;
        __syncthreads();
    }
    if (i < N) g_inc[i] = sh[threadIdx.x];
    if (threadIdx.x == SCAN_CHUNK - 1) g_bsum[blockIdx.x] = sh[SCAN_CHUNK - 1];
}

__global__ __launch_bounds__(256) void k_scanB(int NB) {
    __shared__ int sh[256];
    int t = threadIdx.x;
    int v = (t < NB) ? g_bsum[t] : 0;
    sh[t] = v;
    __syncthreads();
    for (int off = 1; off < 256; off <<= 1) {
        int tv = (t >= off) ? sh[t - off] : 0;
        __syncthreads();
        sh[t] += tv;
        __syncthreads();
    }
    if (t < NB) g_boff[t] = sh[t] - v;   // exclusive
}

__global__ void k_scanC(int N) {
    int i = blockIdx.x * blockDim.x + threadIdx.x;
    if (i >= N) return;
    int b = i / SCAN_CHUNK;
    int inc = g_inc[i] + g_boff[b];
    g_off[i] = inc - g_deg[i];
    if (i == N - 1) g_off[N] = inc;
}

// ---------------- scatter edges into CSR order --------------------------------
__global__ void k_csr_scatter(int EN) {
    int i = blockIdx.x * blockDim.x + threadIdx.x;
    if (i >= EN) return;
    int d = g_dst[i];
    int pos = g_off[d] + atomicAdd(&g_cursor[d], 1);
    g_csr_src[pos] = g_src[i];
}

// ---------------- GEMM + fused attention-logit epilogue ----------------------
// Round-9 structure; ONLY delta: W row slice read as one LDS.128 instead of 4
// scalar LDS (contiguous, 16B-aligned) — halves smem crossbar pressure.
template<int K, int M, int ROWS>
__global__ __launch_bounds__(256) void k_gemm(
    const float* __restrict__ in_ext, int use_int,
    const float* __restrict__ W, const float* __restrict__ bias,
    const float* __restrict__ a_src, const float* __restrict__ a_dst, int N)
{
    constexpr int CG  = M / 4;
    constexpr int RG  = 256 / CG;
    constexpr int RPT = ROWS / RG;
    constexpr int OC  = M / HEADS;
    constexpr int RED = (OC >= 4) ? OC / 4 : 1;
    constexpr int KP  = (K == 128) ? K : (K + 1);
    __shared__ __align__(16) float sW[K * M];
    __shared__ float sIn[ROWS * KP];

    const float* in = use_int ? g_o : in_ext;
    int r0 = blockIdx.x * ROWS;

    for (int i = threadIdx.x; i < K * M; i += 256) sW[i] = W[i];
    for (int i = threadIdx.x; i < ROWS * K; i += 256) {
        int r = i / K, k = i - r * K;
        int gr = r0 + r;
        float v = 0.f;
        if (gr < N) {
            v = in[gr * K + k];
            if (bias) { v += bias[k]; v = fmaxf(v, 0.f); }
        }
        sIn[r * KP + k] = v;
    }
    __syncthreads();

    int cg = threadIdx.x % CG;
    int rg = threadIdx.x / CG;
    float acc[RPT][4];
#pragma unroll
    for (int i = 0; i < RPT; i++)
        acc[i][0] = acc[i][1] = acc[i][2] = acc[i][3] = 0.f;

#pragma unroll 8
    for (int k = 0; k < K; k++) {
        float4 w = *(const float4*)&sW[k * M + cg * 4];
#pragma unroll
        for (int i = 0; i < RPT; i++) {
            float a = sIn[(rg * RPT + i) * KP + k];
            acc[i][0] += a * w.x; acc[i][1] += a * w.y;
            acc[i][2] += a * w.z; acc[i][3] += a * w.w;
        }
    }

    float4 asv = *(const float4*)&a_src[cg * 4];
    float4 adv = *(const float4*)&a_dst[cg * 4];

#pragma unroll
    for (int i = 0; i < RPT; i++) {
        int gr = r0 + rg * RPT + i;
        bool ok = (gr < N);
        if (ok) {
            float4 v = make_float4(acc[i][0], acc[i][1], acc[i][2], acc[i][3]);
            *(float4*)&g_h[gr * M + cg * 4] = v;
        }
        if constexpr (OC >= 4) {
            float vs = acc[i][0]*asv.x + acc[i][1]*asv.y + acc[i][2]*asv.z + acc[i][3]*asv.w;
            float vd = acc[i][0]*adv.x + acc[i][1]*adv.y + acc[i][2]*adv.z + acc[i][3]*adv.w;
#pragma unroll
            for (int o = 1; o < RED; o <<= 1) {
                vs += __shfl_xor_sync(0xffffffffu, vs, o, 32);
                vd += __shfl_xor_sync(0xffffffffu, vd, o, 32);
            }
            if (ok && (cg % RED) == 0) {
                int head = cg / RED;
                g_als[gr * HEADS + head] = vs;
                g_ald[gr * HEADS + head] = vd;
            }
        } else {  // OC == 2: thread's 4 cols span 2 heads
            float vs0 = acc[i][0]*asv.x + acc[i][1]*asv.y;
            float vd0 = acc[i][0]*adv.x + acc[i][1]*adv.y;
            float vs1 = acc[i][2]*asv.z + acc[i][3]*asv.w;
            float vd1 = acc[i][2]*adv.z + acc[i][3]*adv.w;
            if (ok) {
                g_als[gr * HEADS + cg * 2 + 0] = vs0;
                g_ald[gr * HEADS + cg * 2 + 0] = vd0;
                g_als[gr * HEADS + cg * 2 + 1] = vs1;
                g_ald[gr * HEADS + cg * 2 + 1] = vd1;
            }
        }
    }
}

// ---------------- fused softmax + aggregation (round-6/9 proven) --------------
// TPN = F/V threads per node. 8-edge batches preload indices and logits; the
// feature float4 is consumed immediately (register-lean). Softmax shift
// skipped (shift-invariant, O(1) logits).
template<int OC>
__global__ __launch_bounds__(256) void k_agg(int N) {
    constexpr int F   = HEADS * OC;
    constexpr int V   = (OC >= 4) ? 4 : 2;
    constexpr int TPN = F / V;
    constexpr int LPH = OC / V;        // lanes per head
    constexpr int NPB = 256 / TPN;
    int node = blockIdx.x * NPB + threadIdx.x / TPN;
    if (node >= N) node = N - 1;       // clamp: duplicate compute, identical writes
    int t    = threadIdx.x % TPN;
    int head = t / LPH;

    int beg = g_off[node], end = g_off[node + 1];
    float ald_d = g_ald[node * HEADS + head];

    float acc[V];
#pragma unroll
    for (int v = 0; v < V; v++) acc[v] = 0.f;
    float ssum = 0.f;

    int p = beg;
    for (; p + 8 <= end; p += 8) {
        int ss[8];
#pragma unroll
        for (int j = 0; j < 8; j++) ss[j] = g_csr_src[p + j];
        float al[8];
#pragma unroll
        for (int j = 0; j < 8; j++) al[j] = g_als[ss[j] * HEADS + head];
#pragma unroll
        for (int j = 0; j < 8; j++) {
            float ex = __expf(lrelu(al[j] + ald_d));
            ssum += ex;
            const float* hp = &g_h[ss[j] * F + t * V];
            if constexpr (V == 4) {
                float4 hv = *(const float4*)hp;
                acc[0] += ex * hv.x; acc[1] += ex * hv.y;
                acc[2] += ex * hv.z; acc[3] += ex * hv.w;
            } else {
                float2 hv = *(const float2*)hp;
                acc[0] += ex * hv.x; acc[1] += ex * hv.y;
            }
        }
    }
    for (; p < end; p++) {
        int s = g_csr_src[p];
        float ex = __expf(lrelu(g_als[s * HEADS + head] + ald_d));
        ssum += ex;
        const float* hp = &g_h[s * F + t * V];
        if constexpr (V == 4) {
            float4 hv = *(const float4*)hp;
            acc[0] += ex * hv.x; acc[1] += ex * hv.y;
            acc[2] += ex * hv.z; acc[3] += ex * hv.w;
        } else {
            float2 hv = *(const float2*)hp;
            acc[0] += ex * hv.x; acc[1] += ex * hv.y;
        }
    }

    float inv = 1.f / (ssum + 1e-16f);
    float* op = &g_o[node * F + t * V];
    if constexpr (V == 4)
        *(float4*)op = make_float4(acc[0] * inv, acc[1] * inv, acc[2] * inv, acc[3] * inv);
    else
        *(float2*)op = make_float2(acc[0] * inv, acc[1] * inv);
}

// ---------------- pooling + fc -----------------------------------------------
__global__ void k_pool(const void* __restrict__ batch,
                       const float* __restrict__ b4, int N) {
    int n = blockIdx.x * blockDim.x + threadIdx.x;
    if (n >= N) return;
    int g = g_is64 ? (int)((const long long*)batch)[n]
                   : ((const int*)batch)[n];
#pragma unroll
    for (int j = 0; j < 8; j++) {
        float v = fmaxf(g_o[n * 8 + j] + b4[j], 0.f);
        atomicAdd(&g_psum[g * 8 + j], v);
    }
    atomicAdd(&g_pcnt[g], 1.f);
}

__global__ void k_fc(const float* __restrict__ Wfc,
                     const float* __restrict__ bfc, float* __restrict__ out) {
    int b = blockIdx.x, o = threadIdx.x;  // grid 64, block 32
    float c = fmaxf(g_pcnt[b], 1.f);
    float acc = bfc[o];
#pragma unroll
    for (int j = 0; j < 8; j++)
        acc += (g_psum[b * 8 + j] / c) * Wfc[j * 32 + o];
    out[b * 32 + o] = acc;
}

// ---------------- launch ------------------------------------------------------
extern "C" void kernel_launch(void* const* d_in, const int* in_sizes, int n_in,
                              void* d_out, int out_size) {
    const float* x    = (const float*)d_in[0];
    const void*  ei   = d_in[1];
    const void*  batch= d_in[2];
    const float* W1  = (const float*)d_in[3];
    const float* as1 = (const float*)d_in[4];
    const float* ad1 = (const float*)d_in[5];
    const float* b1  = (const float*)d_in[6];
    const float* W2  = (const float*)d_in[7];
    const float* as2 = (const float*)d_in[8];
    const float* ad2 = (const float*)d_in[9];
    const float* b2  = (const float*)d_in[10];
    const float* W3  = (const float*)d_in[11];
    const float* as3 = (const float*)d_in[12];
    const float* ad3 = (const float*)d_in[13];
    const float* b3  = (const float*)d_in[14];
    const float* W4  = (const float*)d_in[15];
    const float* as4 = (const float*)d_in[16];
    const float* ad4 = (const float*)d_in[17];
    const float* b4  = (const float*)d_in[18];
    const float* Wfc = (const float*)d_in[19];
    const float* bfc = (const float*)d_in[20];
    float* out = (float*)d_out;

    int N  = in_sizes[0] / 128;
    int E  = in_sizes[1] / 2;
    int EN = E + N;

    int nb = (N + 255) / 256;
    int eb = (EN + 255) / 256;
    int NB = (N + SCAN_CHUNK - 1) / SCAN_CHUNK;

    // Side stream + fork/join events, created once on the FIRST call (the
    // correctness run, which is NOT captured) — nothing created inside the
    // graph, no device memory allocated.
    static cudaStream_t s2 = nullptr;
    static cudaEvent_t evFork = nullptr, evJoin = nullptr;
    if (s2 == nullptr) {
        cudaStreamCreateWithFlags(&s2, cudaStreamNonBlocking);
        cudaEventCreateWithFlags(&evFork, cudaEventDisableTiming);
        cudaEventCreateWithFlags(&evJoin, cudaEventDisableTiming);
    }

    // ---- fork: CSR build on s2, GEMM1 on the main stream, concurrently ----
    cudaEventRecord(evFork, 0);
    cudaStreamWaitEvent(s2, evFork, 0);

    k_detect<<<1, 256, 0, s2>>>((const unsigned*)ei, E);
    k_zero<<<nb, 256, 0, s2>>>(N);
    k_hist<<<eb, 256, 0, s2>>>(ei, E, N);
    k_scanA<<<NB, SCAN_CHUNK, 0, s2>>>(N);
    k_scanB<<<1, 256, 0, s2>>>(NB);
    k_scanC<<<nb, 256, 0, s2>>>(N);
    k_csr_scatter<<<eb, 256, 0, s2>>>(EN);

    // layer-1 GEMM runs concurrently on the main stream (depends only on x/W1)
    k_gemm<128, 64, 32><<<(N + 31) / 32, 256>>>(x, 0, W1, nullptr, as1, ad1, N);

    // ---- join: aggregation needs both the CSR and GEMM1 results ----
    cudaEventRecord(evJoin, s2);
    cudaStreamWaitEvent(0, evJoin, 0);

    // ---- layer 1 (F = 64) ----
    k_agg<16><<<(N + 15) / 16, 256>>>(N);

    // ---- layer 2 (in = relu(g_o + b1)), F = 32 ----
    k_gemm<64, 32, 128><<<(N + 127) / 128, 256>>>(nullptr, 1, W2, b1, as2, ad2, N);
    k_agg<8><<<(N + 31) / 32, 256>>>(N);

    // ---- layer 3, F = 16 ----
    k_gemm<32, 16, 256><<<(N + 255) / 256, 256>>>(nullptr, 1, W3, b2, as3, ad3, N);
    k_agg<4><<<(N + 63) / 64, 256>>>(N);

    // ---- layer 4, F = 8 ----
    k_gemm<16, 8, 512><<<(N + 511) / 512, 256>>>(nullptr, 1, W4, b3, as4, ad4, N);
    k_agg<2><<<(N + 63) / 64, 256>>>(N);

    // ---- global mean pool (relu(g_o + b4)) + fc ----
    k_pool<<<nb, 256>>>(batch, b4, N);
    k_fc<<<64, 32>>>(Wfc, bfc, out);
}

// round 12
// speedup vs baseline: 1.0271x; 1.0078x over previous
#include <cuda_runtime.h>

#define HEADS 4
#define NEG_SLOPE 0.2f

static const int N_CAP  = 100000;
static const int EN_CAP = 1700000;
static const int SCAN_CHUNK = 512;

// ---------------- scratch (static device globals; no allocation) -------------
__device__ float g_h  [N_CAP * 64];   // transformed features h = in @ W   [N, F]
__device__ float g_o  [N_CAP * 64];   // aggregated output (next layer in) [N, F]
__device__ float g_als[N_CAP * HEADS];
__device__ float g_ald[N_CAP * HEADS];
__device__ int   g_src[EN_CAP];
__device__ int   g_dst[EN_CAP];
__device__ int   g_csr_src[EN_CAP];
__device__ int   g_deg[N_CAP];
__device__ int   g_inc[N_CAP];
__device__ int   g_off[N_CAP + 1];
__device__ int   g_cursor[N_CAP];
__device__ int   g_bsum[256];
__device__ int   g_boff[256];
__device__ float g_psum[64 * 8];
__device__ float g_pcnt[64];
__device__ int   g_is64;

// ---------------- helpers ----------------------------------------------------
__device__ __forceinline__ float lrelu(float x) { return x > 0.f ? x : NEG_SLOPE * x; }

// ---------------- index-width detection --------------------------------------
__global__ void k_detect(const unsigned* __restrict__ w, int pairs) {
    __shared__ int any;
    if (threadIdx.x == 0) any = 0;
    __syncthreads();
    int lim = pairs < 4096 ? pairs : 4096;
    int local = 0;
    for (int i = threadIdx.x; i < lim; i += blockDim.x)
        if (w[2 * i + 1] != 0u) local = 1;
    if (local) atomicExch(&any, 1);
    __syncthreads();
    if (threadIdx.x == 0) g_is64 = (any == 0) ? 1 : 0;
}

// ---------------- zero transient state ---------------------------------------
__global__ void k_zero(int N) {
    int i = blockIdx.x * blockDim.x + threadIdx.x;
    if (i < N) { g_deg[i] = 0; g_cursor[i] = 0; }
    if (i < 512) g_psum[i] = 0.f;
    if (i < 64)  g_pcnt[i] = 0.f;
}

// ---------------- decode edges + dst histogram --------------------------------
__global__ void k_hist(const void* __restrict__ ei, int E, int N) {
    int i = blockIdx.x * blockDim.x + threadIdx.x;
    int EN = E + N;
    if (i >= EN) return;
    int s, d;
    if (i < E) {
        if (g_is64) {
            const long long* p = (const long long*)ei;
            s = (int)p[i]; d = (int)p[E + i];
        } else {
            const int* p = (const int*)ei;
            s = p[i]; d = p[E + i];
        }
    } else {             // self-loops appended (PyG GATConv behavior)
        s = d = i - E;
    }
    g_src[i] = s;
    g_dst[i] = d;
    atomicAdd(&g_deg[d], 1);
}

// ---------------- 3-phase exclusive scan of g_deg -> g_off --------------------
__global__ __launch_bounds__(SCAN_CHUNK) void k_scanA(int N) {
    __shared__ int sh[SCAN_CHUNK];
    int i = blockIdx.x * SCAN_CHUNK + threadIdx.x;
    int v = (i < N) ? g_deg[i] : 0;
    sh[threadIdx.x] = v;
    __syncthreads();
    for (int off = 1; off < SCAN_CHUNK; off <<= 1) {
        int t = (threadIdx.x >= off) ? sh[threadIdx.x - off] : 0;
        __syncthreads();
        sh[threadIdx.x] += t;
        __syncthreads();
    }
    if (i < N) g_inc[i] = sh[threadIdx.x];
    if (threadIdx.x == SCAN_CHUNK - 1) g_bsum[blockIdx.x] = sh[SCAN_CHUNK - 1];
}

__global__ __launch_bounds__(256) void k_scanB(int NB) {
    __shared__ int sh[256];
    int t = threadIdx.x;
    int v = (t < NB) ? g_bsum[t] : 0;
    sh[t] = v;
    __syncthreads();
    for (int off = 1; off < 256; off <<= 1) {
        int tv = (t >= off) ? sh[t - off] : 0;
        __syncthreads();
        sh[t] += tv;
        __syncthreads();
    }
    if (t < NB) g_boff[t] = sh[t] - v;   // exclusive
}

__global__ void k_scanC(int N) {
    int i = blockIdx.x * blockDim.x + threadIdx.x;
    if (i >= N) return;
    int b = i / SCAN_CHUNK;
    int inc = g_inc[i] + g_boff[b];
    g_off[i] = inc - g_deg[i];
    if (i == N - 1) g_off[N] = inc;
}

// ---------------- scatter edges into CSR order --------------------------------
__global__ void k_csr_scatter(int EN) {
    int i = blockIdx.x * blockDim.x + threadIdx.x;
    if (i >= EN) return;
    int d = g_dst[i];
    int pos = g_off[d] + atomicAdd(&g_cursor[d], 1);
    g_csr_src[pos] = g_src[i];
}

// ---------------- GEMM + fused attention-logit epilogue (round-9 exact) ------
// g_h = act(in [+bias]) @ W ; g_als/g_ald = per-head dot(h_row, a_src/a_dst).
template<int K, int M, int ROWS>
__global__ __launch_bounds__(256) void k_gemm(
    const float* __restrict__ in_ext, int use_int,
    const float* __restrict__ W, const float* __restrict__ bias,
    const float* __restrict__ a_src, const float* __restrict__ a_dst, int N)
{
    constexpr int CG  = M / 4;
    constexpr int RG  = 256 / CG;
    constexpr int RPT = ROWS / RG;
    constexpr int OC  = M / HEADS;
    constexpr int RED = (OC >= 4) ? OC / 4 : 1;
    constexpr int KP  = (K == 128) ? K : (K + 1);
    __shared__ float sW[K * M];
    __shared__ float sIn[ROWS * KP];

    const float* in = use_int ? g_o : in_ext;
    int r0 = blockIdx.x * ROWS;

    for (int i = threadIdx.x; i < K * M; i += 256) sW[i] = W[i];
    for (int i = threadIdx.x; i < ROWS * K; i += 256) {
        int r = i / K, k = i - r * K;
        int gr = r0 + r;
        float v = 0.f;
        if (gr < N) {
            v = in[gr * K + k];
            if (bias) { v += bias[k]; v = fmaxf(v, 0.f); }
        }
        sIn[r * KP + k] = v;
    }
    __syncthreads();

    int cg = threadIdx.x % CG;
    int rg = threadIdx.x / CG;
    float acc[RPT][4];
#pragma unroll
    for (int i = 0; i < RPT; i++)
        acc[i][0] = acc[i][1] = acc[i][2] = acc[i][3] = 0.f;

#pragma unroll 8
    for (int k = 0; k < K; k++) {
        float w0 = sW[k * M + cg * 4 + 0];
        float w1 = sW[k * M + cg * 4 + 1];
        float w2 = sW[k * M + cg * 4 + 2];
        float w3 = sW[k * M + cg * 4 + 3];
#pragma unroll
        for (int i = 0; i < RPT; i++) {
            float a = sIn[(rg * RPT + i) * KP + k];
            acc[i][0] += a * w0; acc[i][1] += a * w1;
            acc[i][2] += a * w2; acc[i][3] += a * w3;
        }
    }

    float4 asv = *(const float4*)&a_src[cg * 4];
    float4 adv = *(const float4*)&a_dst[cg * 4];

#pragma unroll
    for (int i = 0; i < RPT; i++) {
        int gr = r0 + rg * RPT + i;
        bool ok = (gr < N);
        if (ok) {
            float4 v = make_float4(acc[i][0], acc[i][1], acc[i][2], acc[i][3]);
            *(float4*)&g_h[gr * M + cg * 4] = v;
        }
        if constexpr (OC >= 4) {
            float vs = acc[i][0]*asv.x + acc[i][1]*asv.y + acc[i][2]*asv.z + acc[i][3]*asv.w;
            float vd = acc[i][0]*adv.x + acc[i][1]*adv.y + acc[i][2]*adv.z + acc[i][3]*adv.w;
#pragma unroll
            for (int o = 1; o < RED; o <<= 1) {
                vs += __shfl_xor_sync(0xffffffffu, vs, o, 32);
                vd += __shfl_xor_sync(0xffffffffu, vd, o, 32);
            }
            if (ok && (cg % RED) == 0) {
                int head = cg / RED;
                g_als[gr * HEADS + head] = vs;
                g_ald[gr * HEADS + head] = vd;
            }
        } else {  // OC == 2: thread's 4 cols span 2 heads
            float vs0 = acc[i][0]*asv.x + acc[i][1]*asv.y;
            float vd0 = acc[i][0]*adv.x + acc[i][1]*adv.y;
            float vs1 = acc[i][2]*asv.z + acc[i][3]*asv.w;
            float vd1 = acc[i][2]*adv.z + acc[i][3]*adv.w;
            if (ok) {
                g_als[gr * HEADS + cg * 2 + 0] = vs0;
                g_ald[gr * HEADS + cg * 2 + 0] = vd0;
                g_als[gr * HEADS + cg * 2 + 1] = vs1;
                g_ald[gr * HEADS + cg * 2 + 1] = vd1;
            }
        }
    }
}

// ---------------- fused softmax + aggregation (round-9 core + in-block sort) --
// Each block bitonic-sorts its NPB-node window by degree in smem, then lane
// groups take nodes in sorted order: warp-co-resident nodes get near-equal
// trip counts (kills max-of-degrees divergence) while all per-group access
// patterns (contiguous row writes, sequential CSR walks) are unchanged.
// 8-edge batches preload indices and logits; feature float4 consumed
// immediately. Softmax shift skipped (shift-invariant, O(1) logits).
template<int OC>
__global__ __launch_bounds__(256) void k_agg(int N) {
    constexpr int F   = HEADS * OC;
    constexpr int V   = (OC >= 4) ? 4 : 2;
    constexpr int TPN = F / V;
    constexpr int LPH = OC / V;        // lanes per head
    constexpr int NPB = 256 / TPN;     // 16 / 32 / 64 / 64
    __shared__ int s_key[NPB];

    int base = blockIdx.x * NPB;

    // load (deg << 8 | slot) keys for this block's node window
    if (threadIdx.x < NPB) {
        int n = base + threadIdx.x;
        if (n >= N) n = N - 1;
        int d = g_off[n + 1] - g_off[n];
        s_key[threadIdx.x] = (d << 8) | threadIdx.x;
    }
    __syncthreads();

    // bitonic sort ascending (NPB is a power of two <= 64)
#pragma unroll
    for (int k2 = 2; k2 <= NPB; k2 <<= 1) {
#pragma unroll
        for (int j = k2 >> 1; j > 0; j >>= 1) {
            if (threadIdx.x < NPB) {
                int i = threadIdx.x, ixj = i ^ j;
                if (ixj > i) {
                    int a = s_key[i], b = s_key[ixj];
                    bool up = ((i & k2) == 0);
                    if (up ? (a > b) : (a < b)) { s_key[i] = b; s_key[ixj] = a; }
                }
            }
            __syncthreads();
        }
    }

    int slot = threadIdx.x / TPN;
    int node = base + (s_key[slot] & 255);
    if (node >= N) node = N - 1;       // clamp: duplicate compute, identical writes
    int t    = threadIdx.x % TPN;
    int head = t / LPH;

    int beg = g_off[node], end = g_off[node + 1];
    float ald_d = g_ald[node * HEADS + head];

    float acc[V];
#pragma unroll
    for (int v = 0; v < V; v++) acc[v] = 0.f;
    float ssum = 0.f;

    int p = beg;
    for (; p + 8 <= end; p += 8) {
        int ss[8];
#pragma unroll
        for (int j = 0; j < 8; j++) ss[j] = g_csr_src[p + j];
        float al[8];
#pragma unroll
        for (int j = 0; j < 8; j++) al[j] = g_als[ss[j] * HEADS + head];
#pragma unroll
        for (int j = 0; j < 8; j++) {
            float ex = __expf(lrelu(al[j] + ald_d));
            ssum += ex;
            const float* hp = &g_h[ss[j] * F + t * V];
            if constexpr (V == 4) {
                float4 hv = *(const float4*)hp;
                acc[0] += ex * hv.x; acc[1] += ex * hv.y;
                acc[2] += ex * hv.z; acc[3] += ex * hv.w;
            } else {
                float2 hv = *(const float2*)hp;
                acc[0] += ex * hv.x; acc[1] += ex * hv.y;
            }
        }
    }
    for (; p < end; p++) {
        int s = g_csr_src[p];
        float ex = __expf(lrelu(g_als[s * HEADS + head] + ald_d));
        ssum += ex;
        const float* hp = &g_h[s * F + t * V];
        if constexpr (V == 4) {
            float4 hv = *(const float4*)hp;
            acc[0] += ex * hv.x; acc[1] += ex * hv.y;
            acc[2] += ex * hv.z; acc[3] += ex * hv.w;
        } else {
            float2 hv = *(const float2*)hp;
            acc[0] += ex * hv.x; acc[1] += ex * hv.y;
        }
    }

    float inv = 1.f / (ssum + 1e-16f);
    float* op = &g_o[node * F + t * V];
    if constexpr (V == 4)
        *(float4*)op = make_float4(acc[0] * inv, acc[1] * inv, acc[2] * inv, acc[3] * inv);
    else
        *(float2*)op = make_float2(acc[0] * inv, acc[1] * inv);
}

// ---------------- pooling + fc -----------------------------------------------
__global__ void k_pool(const void* __restrict__ batch,
                       const float* __restrict__ b4, int N) {
    int n = blockIdx.x * blockDim.x + threadIdx.x;
    if (n >= N) return;
    int g = g_is64 ? (int)((const long long*)batch)[n]
                   : ((const int*)batch)[n];
#pragma unroll
    for (int j = 0; j < 8; j++) {
        float v = fmaxf(g_o[n * 8 + j] + b4[j], 0.f);
        atomicAdd(&g_psum[g * 8 + j], v);
    }
    atomicAdd(&g_pcnt[g], 1.f);
}

__global__ void k_fc(const float* __restrict__ Wfc,
                     const float* __restrict__ bfc, float* __restrict__ out) {
    int b = blockIdx.x, o = threadIdx.x;  // grid 64, block 32
    float c = fmaxf(g_pcnt[b], 1.f);
    float acc = bfc[o];
#pragma unroll
    for (int j = 0; j < 8; j++)
        acc += (g_psum[b * 8 + j] / c) * Wfc[j * 32 + o];
    out[b * 32 + o] = acc;
}

// ---------------- launch ------------------------------------------------------
extern "C" void kernel_launch(void* const* d_in, const int* in_sizes, int n_in,
                              void* d_out, int out_size) {
    const float* x    = (const float*)d_in[0];
    const void*  ei   = d_in[1];
    const void*  batch= d_in[2];
    const float* W1  = (const float*)d_in[3];
    const float* as1 = (const float*)d_in[4];
    const float* ad1 = (const float*)d_in[5];
    const float* b1  = (const float*)d_in[6];
    const float* W2  = (const float*)d_in[7];
    const float* as2 = (const float*)d_in[8];
    const float* ad2 = (const float*)d_in[9];
    const float* b2  = (const float*)d_in[10];
    const float* W3  = (const float*)d_in[11];
    const float* as3 = (const float*)d_in[12];
    const float* ad3 = (const float*)d_in[13];
    const float* b3  = (const float*)d_in[14];
    const float* W4  = (const float*)d_in[15];
    const float* as4 = (const float*)d_in[16];
    const float* ad4 = (const float*)d_in[17];
    const float* b4  = (const float*)d_in[18];
    const float* Wfc = (const float*)d_in[19];
    const float* bfc = (const float*)d_in[20];
    float* out = (float*)d_out;

    int N  = in_sizes[0] / 128;
    int E  = in_sizes[1] / 2;
    int EN = E + N;

    int nb = (N + 255) / 256;
    int eb = (EN + 255) / 256;
    int NB = (N + SCAN_CHUNK - 1) / SCAN_CHUNK;

    // Side stream + fork/join events, created once on the FIRST call (the
    // correctness run, which is NOT captured) — nothing created inside the
    // graph, no device memory allocated.
    static cudaStream_t s2 = nullptr;
    static cudaEvent_t evFork = nullptr, evJoin = nullptr;
    if (s2 == nullptr) {
        cudaStreamCreateWithFlags(&s2, cudaStreamNonBlocking);
        cudaEventCreateWithFlags(&evFork, cudaEventDisableTiming);
        cudaEventCreateWithFlags(&evJoin, cudaEventDisableTiming);
    }

    // ---- fork: CSR build on s2, GEMM1 on the main stream, concurrently ----
    cudaEventRecord(evFork, 0);
    cudaStreamWaitEvent(s2, evFork, 0);

    k_detect<<<1, 256, 0, s2>>>((const unsigned*)ei, E);
    k_zero<<<nb, 256, 0, s2>>>(N);
    k_hist<<<eb, 256, 0, s2>>>(ei, E, N);
    k_scanA<<<NB, SCAN_CHUNK, 0, s2>>>(N);
    k_scanB<<<1, 256, 0, s2>>>(NB);
    k_scanC<<<nb, 256, 0, s2>>>(N);
    k_csr_scatter<<<eb, 256, 0, s2>>>(EN);

    // layer-1 GEMM runs concurrently on the main stream (depends only on x/W1)
    k_gemm<128, 64, 32><<<(N + 31) / 32, 256>>>(x, 0, W1, nullptr, as1, ad1, N);

    // ---- join: aggregation needs both the CSR and GEMM1 results ----
    cudaEventRecord(evJoin, s2);
    cudaStreamWaitEvent(0, evJoin, 0);

    // ---- layer 1 (F = 64) ----
    k_agg<16><<<(N + 15) / 16, 256>>>(N);

    // ---- layer 2 (in = relu(g_o + b1)), F = 32 ----
    k_gemm<64, 32, 128><<<(N + 127) / 128, 256>>>(nullptr, 1, W2, b1, as2, ad2, N);
    k_agg<8><<<(N + 31) / 32, 256>>>(N);

    // ---- layer 3, F = 16 ----
    k_gemm<32, 16, 256><<<(N + 255) / 256, 256>>>(nullptr, 1, W3, b2, as3, ad3, N);
    k_agg<4><<<(N + 63) / 64, 256>>>(N);

    // ---- layer 4, F = 8 ----
    k_gemm<16, 8, 512><<<(N + 511) / 512, 256>>>(nullptr, 1, W4, b3, as4, ad4, N);
    k_agg<2><<<(N + 63) / 64, 256>>>(N);

    // ---- global mean pool (relu(g_o + b4)) + fc ----
    k_pool<<<nb, 256>>>(batch, b4, N);
    k_fc<<<64, 32>>>(Wfc, bfc, out);
}

// round 13
// speedup vs baseline: 1.2878x; 1.2538x over previous
#include <cuda_runtime.h>

#define HEADS 4
#define NEG_SLOPE 0.2f

static const int N_CAP  = 100000;
static const int EN_CAP = 1700000;
static const int SCAN_CHUNK = 512;

// ---------------- scratch (static device globals; no allocation) -------------
__device__ float g_h  [N_CAP * 64];   // transformed features h = in @ W   [N, F]
__device__ float g_o  [N_CAP * 64];   // aggregated output (next layer in) [N, F]
__device__ float g_als[N_CAP * HEADS];
__device__ float g_ald[N_CAP * HEADS];
__device__ int   g_src[EN_CAP];
__device__ int   g_dst[EN_CAP];
__device__ int   g_csr_src[EN_CAP];
__device__ int   g_deg[N_CAP];
__device__ int   g_inc[N_CAP];
__device__ int   g_off[N_CAP + 1];
__device__ int   g_cursor[N_CAP];
__device__ int   g_bsum[256];
__device__ int   g_boff[256];
__device__ float g_psum[64 * 8];
__device__ float g_pcnt[64];
__device__ int   g_is64;

// ---------------- helpers ----------------------------------------------------
__device__ __forceinline__ float lrelu(float x) { return x > 0.f ? x : NEG_SLOPE * x; }

// ---------------- index-width detection --------------------------------------
__global__ void k_detect(const unsigned* __restrict__ w, int pairs) {
    __shared__ int any;
    if (threadIdx.x == 0) any = 0;
    __syncthreads();
    int lim = pairs < 4096 ? pairs : 4096;
    int local = 0;
    for (int i = threadIdx.x; i < lim; i += blockDim.x)
        if (w[2 * i + 1] != 0u) local = 1;
    if (local) atomicExch(&any, 1);
    __syncthreads();
    if (threadIdx.x == 0) g_is64 = (any == 0) ? 1 : 0;
}

// ---------------- zero transient state ---------------------------------------
__global__ void k_zero(int N) {
    int i = blockIdx.x * blockDim.x + threadIdx.x;
    if (i < N) { g_deg[i] = 0; g_cursor[i] = 0; }
    if (i < 512) g_psum[i] = 0.f;
    if (i < 64)  g_pcnt[i] = 0.f;
}

// ---------------- decode edges + dst histogram --------------------------------
__global__ void k_hist(const void* __restrict__ ei, int E, int N) {
    int i = blockIdx.x * blockDim.x + threadIdx.x;
    int EN = E + N;
    if (i >= EN) return;
    int s, d;
    if (i < E) {
        if (g_is64) {
            const long long* p = (const long long*)ei;
            s = (int)p[i]; d = (int)p[E + i];
        } else {
            const int* p = (const int*)ei;
            s = p[i]; d = p[E + i];
        }
    } else {             // self-loops appended (PyG GATConv behavior)
        s = d = i - E;
    }
    g_src[i] = s;
    g_dst[i] = d;
    atomicAdd(&g_deg[d], 1);
}

// ---------------- 3-phase exclusive scan of g_deg -> g_off --------------------
__global__ __launch_bounds__(SCAN_CHUNK) void k_scanA(int N) {
    __shared__ int sh[SCAN_CHUNK];
    int i = blockIdx.x * SCAN_CHUNK + threadIdx.x;
    int v = (i < N) ? g_deg[i] : 0;
    sh[threadIdx.x] = v;
    __syncthreads();
    for (int off = 1; off < SCAN_CHUNK; off <<= 1) {
        int t = (threadIdx.x >= off) ? sh[threadIdx.x - off] : 0;
        __syncthreads();
        sh[threadIdx.x] += t;
        __syncthreads();
    }
    if (i < N) g_inc[i] = sh[threadIdx.x];
    if (threadIdx.x == SCAN_CHUNK - 1) g_bsum[blockIdx.x] = sh[SCAN_CHUNK - 1];
}

__global__ __launch_bounds__(256) void k_scanB(int NB) {
    __shared__ int sh[256];
    int t = threadIdx.x;
    int v = (t < NB) ? g_bsum[t] : 0;
    sh[t] = v;
    __syncthreads();
    for (int off = 1; off < 256; off <<= 1) {
        int tv = (t >= off) ? sh[t - off] : 0;
        __syncthreads();
        sh[t] += tv;
        __syncthreads();
    }
    if (t < NB) g_boff[t] = sh[t] - v;   // exclusive
}

__global__ void k_scanC(int N) {
    int i = blockIdx.x * blockDim.x + threadIdx.x;
    if (i >= N) return;
    int b = i / SCAN_CHUNK;
    int inc = g_inc[i] + g_boff[b];
    g_off[i] = inc - g_deg[i];
    if (i == N - 1) g_off[N] = inc;
}

// ---------------- scatter edges into CSR order --------------------------------
__global__ void k_csr_scatter(int EN) {
    int i = blockIdx.x * blockDim.x + threadIdx.x;
    if (i >= EN) return;
    int d = g_dst[i];
    int pos = g_off[d] + atomicAdd(&g_cursor[d], 1);
    g_csr_src[pos] = g_src[i];
}

// ---------------- GEMM + fused attention-logit epilogue (round-9 exact) ------
// g_h = act(in [+bias]) @ W ; g_als/g_ald = per-head dot(h_row, a_src/a_dst).
template<int K, int M, int ROWS>
__global__ __launch_bounds__(256) void k_gemm(
    const float* __restrict__ in_ext, int use_int,
    const float* __restrict__ W, const float* __restrict__ bias,
    const float* __restrict__ a_src, const float* __restrict__ a_dst, int N)
{
    constexpr int CG  = M / 4;
    constexpr int RG  = 256 / CG;
    constexpr int RPT = ROWS / RG;
    constexpr int OC  = M / HEADS;
    constexpr int RED = (OC >= 4) ? OC / 4 : 1;
    constexpr int KP  = (K == 128) ? K : (K + 1);
    __shared__ float sW[K * M];
    __shared__ float sIn[ROWS * KP];

    const float* in = use_int ? g_o : in_ext;
    int r0 = blockIdx.x * ROWS;

    for (int i = threadIdx.x; i < K * M; i += 256) sW[i] = W[i];
    for (int i = threadIdx.x; i < ROWS * K; i += 256) {
        int r = i / K, k = i - r * K;
        int gr = r0 + r;
        float v = 0.f;
        if (gr < N) {
            v = in[gr * K + k];
            if (bias) { v += bias[k]; v = fmaxf(v, 0.f); }
        }
        sIn[r * KP + k] = v;
    }
    __syncthreads();

    int cg = threadIdx.x % CG;
    int rg = threadIdx.x / CG;
    float acc[RPT][4];
#pragma unroll
    for (int i = 0; i < RPT; i++)
        acc[i][0] = acc[i][1] = acc[i][2] = acc[i][3] = 0.f;

#pragma unroll 8
    for (int k = 0; k < K; k++) {
        float w0 = sW[k * M + cg * 4 + 0];
        float w1 = sW[k * M + cg * 4 + 1];
        float w2 = sW[k * M + cg * 4 + 2];
        float w3 = sW[k * M + cg * 4 + 3];
#pragma unroll
        for (int i = 0; i < RPT; i++) {
            float a = sIn[(rg * RPT + i) * KP + k];
            acc[i][0] += a * w0; acc[i][1] += a * w1;
            acc[i][2] += a * w2; acc[i][3] += a * w3;
        }
    }

    float4 asv = *(const float4*)&a_src[cg * 4];
    float4 adv = *(const float4*)&a_dst[cg * 4];

#pragma unroll
    for (int i = 0; i < RPT; i++) {
        int gr = r0 + rg * RPT + i;
        bool ok = (gr < N);
        if (ok) {
            float4 v = make_float4(acc[i][0], acc[i][1], acc[i][2], acc[i][3]);
            *(float4*)&g_h[gr * M + cg * 4] = v;
        }
        if constexpr (OC >= 4) {
            float vs = acc[i][0]*asv.x + acc[i][1]*asv.y + acc[i][2]*asv.z + acc[i][3]*asv.w;
            float vd = acc[i][0]*adv.x + acc[i][1]*adv.y + acc[i][2]*adv.z + acc[i][3]*adv.w;
#pragma unroll
            for (int o = 1; o < RED; o <<= 1) {
                vs += __shfl_xor_sync(0xffffffffu, vs, o, 32);
                vd += __shfl_xor_sync(0xffffffffu, vd, o, 32);
            }
            if (ok && (cg % RED) == 0) {
                int head = cg / RED;
                g_als[gr * HEADS + head] = vs;
                g_ald[gr * HEADS + head] = vd;
            }
        } else {  // OC == 2: thread's 4 cols span 2 heads
            float vs0 = acc[i][0]*asv.x + acc[i][1]*asv.y;
            float vd0 = acc[i][0]*adv.x + acc[i][1]*adv.y;
            float vs1 = acc[i][2]*asv.z + acc[i][3]*asv.w;
            float vd1 = acc[i][2]*adv.z + acc[i][3]*adv.w;
            if (ok) {
                g_als[gr * HEADS + cg * 2 + 0] = vs0;
                g_ald[gr * HEADS + cg * 2 + 0] = vd0;
                g_als[gr * HEADS + cg * 2 + 1] = vs1;
                g_ald[gr * HEADS + cg * 2 + 1] = vd1;
            }
        }
    }
}

// ---------------- fused softmax + aggregation (round-9 exact) -----------------
// TPN = F/V threads per node. 8-edge batches preload indices and logits; the
// feature float4 is consumed immediately (register-lean). Softmax shift
// skipped (shift-invariant, O(1) logits).
template<int OC>
__global__ __launch_bounds__(256) void k_agg(int N) {
    constexpr int F   = HEADS * OC;
    constexpr int V   = (OC >= 4) ? 4 : 2;
    constexpr int TPN = F / V;
    constexpr int LPH = OC / V;        // lanes per head
    constexpr int NPB = 256 / TPN;
    int node = blockIdx.x * NPB + threadIdx.x / TPN;
    if (node >= N) node = N - 1;       // clamp: duplicate compute, identical writes
    int t    = threadIdx.x % TPN;
    int head = t / LPH;

    int beg = g_off[node], end = g_off[node + 1];
    float ald_d = g_ald[node * HEADS + head];

    float acc[V];
#pragma unroll
    for (int v = 0; v < V; v++) acc[v] = 0.f;
    float ssum = 0.f;

    int p = beg;
    for (; p + 8 <= end; p += 8) {
        int ss[8];
#pragma unroll
        for (int j = 0; j < 8; j++) ss[j] = g_csr_src[p + j];
        float al[8];
#pragma unroll
        for (int j = 0; j < 8; j++) al[j] = g_als[ss[j] * HEADS + head];
#pragma unroll
        for (int j = 0; j < 8; j++) {
            float ex = __expf(lrelu(al[j] + ald_d));
            ssum += ex;
            const float* hp = &g_h[ss[j] * F + t * V];
            if constexpr (V == 4) {
                float4 hv = *(const float4*)hp;
                acc[0] += ex * hv.x; acc[1] += ex * hv.y;
                acc[2] += ex * hv.z; acc[3] += ex * hv.w;
            } else {
                float2 hv = *(const float2*)hp;
                acc[0] += ex * hv.x; acc[1] += ex * hv.y;
            }
        }
    }
    for (; p < end; p++) {
        int s = g_csr_src[p];
        float ex = __expf(lrelu(g_als[s * HEADS + head] + ald_d));
        ssum += ex;
        const float* hp = &g_h[s * F + t * V];
        if constexpr (V == 4) {
            float4 hv = *(const float4*)hp;
            acc[0] += ex * hv.x; acc[1] += ex * hv.y;
            acc[2] += ex * hv.z; acc[3] += ex * hv.w;
        } else {
            float2 hv = *(const float2*)hp;
            acc[0] += ex * hv.x; acc[1] += ex * hv.y;
        }
    }

    float inv = 1.f / (ssum + 1e-16f);
    float* op = &g_o[node * F + t * V];
    if constexpr (V == 4)
        *(float4*)op = make_float4(acc[0] * inv, acc[1] * inv, acc[2] * inv, acc[3] * inv);
    else
        *(float2*)op = make_float2(acc[0] * inv, acc[1] * inv);
}

// ---------------- layer-4 agg with FUSED mean-pool epilogue -------------------
// Same structure as k_agg<2>, but instead of writing g_o it applies
// relu(v + b4) and atomically accumulates into g_psum / g_pcnt. Tail-clamped
// duplicate groups are masked (atomics are not idempotent).
__global__ __launch_bounds__(256) void k_agg_pool(
    const void* __restrict__ batch, const float* __restrict__ b4, int N) {
    constexpr int F   = 8;
    constexpr int V   = 2;
    constexpr int TPN = 4;
    constexpr int NPB = 64;
    int raw  = blockIdx.x * NPB + threadIdx.x / TPN;
    bool valid = (raw < N);
    int node = valid ? raw : N - 1;
    int t    = threadIdx.x % TPN;
    int head = t;                       // LPH == 1

    int beg = g_off[node], end = g_off[node + 1];
    float ald_d = g_ald[node * HEADS + head];

    float acc0 = 0.f, acc1 = 0.f, ssum = 0.f;

    int p = beg;
    for (; p + 8 <= end; p += 8) {
        int ss[8];
#pragma unroll
        for (int j = 0; j < 8; j++) ss[j] = g_csr_src[p + j];
        float al[8];
#pragma unroll
        for (int j = 0; j < 8; j++) al[j] = g_als[ss[j] * HEADS + head];
#pragma unroll
        for (int j = 0; j < 8; j++) {
            float ex = __expf(lrelu(al[j] + ald_d));
            ssum += ex;
            float2 hv = *(const float2*)&g_h[ss[j] * F + t * V];
            acc0 += ex * hv.x; acc1 += ex * hv.y;
        }
    }
    for (; p < end; p++) {
        int s = g_csr_src[p];
        float ex = __expf(lrelu(g_als[s * HEADS + head] + ald_d));
        ssum += ex;
        float2 hv = *(const float2*)&g_h[s * F + t * V];
        acc0 += ex * hv.x; acc1 += ex * hv.y;
    }

    float inv = 1.f / (ssum + 1e-16f);
    float v0 = fmaxf(acc0 * inv + b4[t * V + 0], 0.f);
    float v1 = fmaxf(acc1 * inv + b4[t * V + 1], 0.f);

    if (valid) {
        int g = g_is64 ? (int)((const long long*)batch)[node]
                       : ((const int*)batch)[node];
        atomicAdd(&g_psum[g * F + t * V + 0], v0);
        atomicAdd(&g_psum[g * F + t * V + 1], v1);
        if (t == 0) atomicAdd(&g_pcnt[g], 1.f);
    }
}

// ---------------- fc ----------------------------------------------------------
__global__ void k_fc(const float* __restrict__ Wfc,
                     const float* __restrict__ bfc, float* __restrict__ out) {
    int b = blockIdx.x, o = threadIdx.x;  // grid 64, block 32
    float c = fmaxf(g_pcnt[b], 1.f);
    float acc = bfc[o];
#pragma unroll
    for (int j = 0; j < 8; j++)
        acc += (g_psum[b * 8 + j] / c) * Wfc[j * 32 + o];
    out[b * 32 + o] = acc;
}

// ---------------- launch ------------------------------------------------------
extern "C" void kernel_launch(void* const* d_in, const int* in_sizes, int n_in,
                              void* d_out, int out_size) {
    const float* x    = (const float*)d_in[0];
    const void*  ei   = d_in[1];
    const void*  batch= d_in[2];
    const float* W1  = (const float*)d_in[3];
    const float* as1 = (const float*)d_in[4];
    const float* ad1 = (const float*)d_in[5];
    const float* b1  = (const float*)d_in[6];
    const float* W2  = (const float*)d_in[7];
    const float* as2 = (const float*)d_in[8];
    const float* ad2 = (const float*)d_in[9];
    const float* b2  = (const float*)d_in[10];
    const float* W3  = (const float*)d_in[11];
    const float* as3 = (const float*)d_in[12];
    const float* ad3 = (const float*)d_in[13];
    const float* b3  = (const float*)d_in[14];
    const float* W4  = (const float*)d_in[15];
    const float* as4 = (const float*)d_in[16];
    const float* ad4 = (const float*)d_in[17];
    const float* b4  = (const float*)d_in[18];
    const float* Wfc = (const float*)d_in[19];
    const float* bfc = (const float*)d_in[20];
    float* out = (float*)d_out;

    int N  = in_sizes[0] / 128;
    int E  = in_sizes[1] / 2;
    int EN = E + N;

    int nb = (N + 255) / 256;
    int eb = (EN + 255) / 256;
    int NB = (N + SCAN_CHUNK - 1) / SCAN_CHUNK;

    // Side stream + fork/join events, created once on the FIRST call (the
    // correctness run, which is NOT captured) — nothing created inside the
    // graph, no device memory allocated.
    static cudaStream_t s2 = nullptr;
    static cudaEvent_t evFork = nullptr, evJoin = nullptr;
    if (s2 == nullptr) {
        cudaStreamCreateWithFlags(&s2, cudaStreamNonBlocking);
        cudaEventCreateWithFlags(&evFork, cudaEventDisableTiming);
        cudaEventCreateWithFlags(&evJoin, cudaEventDisableTiming);
    }

    // ---- fork: CSR build on s2, GEMM1 on the main stream, concurrently ----
    cudaEventRecord(evFork, 0);
    cudaStreamWaitEvent(s2, evFork, 0);

    k_detect<<<1, 256, 0, s2>>>((const unsigned*)ei, E);
    k_zero<<<nb, 256, 0, s2>>>(N);
    k_hist<<<eb, 256, 0, s2>>>(ei, E, N);
    k_scanA<<<NB, SCAN_CHUNK, 0, s2>>>(N);
    k_scanB<<<1, 256, 0, s2>>>(NB);
    k_scanC<<<nb, 256, 0, s2>>>(N);
    k_csr_scatter<<<eb, 256, 0, s2>>>(EN);

    // layer-1 GEMM runs concurrently on the main stream (depends only on x/W1)
    k_gemm<128, 64, 32><<<(N + 31) / 32, 256>>>(x, 0, W1, nullptr, as1, ad1, N);

    // ---- join: aggregation needs both the CSR and GEMM1 results ----
    cudaEventRecord(evJoin, s2);
    cudaStreamWaitEvent(0, evJoin, 0);

    // ---- layer 1 (F = 64) ----
    k_agg<16><<<(N + 15) / 16, 256>>>(N);

    // ---- layer 2 (in = relu(g_o + b1)), F = 32 ----
    k_gemm<64, 32, 128><<<(N + 127) / 128, 256>>>(nullptr, 1, W2, b1, as2, ad2, N);
    k_agg<8><<<(N + 31) / 32, 256>>>(N);

    // ---- layer 3, F = 16 ----
    k_gemm<32, 16, 256><<<(N + 255) / 256, 256>>>(nullptr, 1, W3, b2, as3, ad3, N);
    k_agg<4><<<(N + 63) / 64, 256>>>(N);

    // ---- layer 4, F = 8: agg with fused mean-pool ----
    k_gemm<16, 8, 512><<<(N + 511) / 512, 256>>>(nullptr, 1, W4, b3, as4, ad4, N);
    k_agg_pool<<<(N + 63) / 64, 256>>>(batch, b4, N);

    // ---- fc ----
    k_fc<<<64, 32>>>(Wfc, bfc, out);
}

// round 15
// speedup vs baseline: 1.3390x; 1.0397x over previous
#include <cuda_runtime.h>

#define HEADS 4
#define NEG_SLOPE 0.2f

static const int N_CAP  = 100000;
static const int EN_CAP = 1700000;
static const int SCAN_CHUNK = 512;

// ---------------- scratch (static device globals; no allocation) -------------
__device__ float g_h  [N_CAP * 64];   // feature buffer A
__device__ float g_o  [N_CAP * 64];   // feature buffer B (o1, then h3)
__device__ float g_als[N_CAP * HEADS];   // logit buffer A
__device__ float g_ald[N_CAP * HEADS];
__device__ float g_als2[N_CAP * HEADS];  // logit buffer B (layer-3)
__device__ float g_ald2[N_CAP * HEADS];
__device__ int   g_src[EN_CAP];
__device__ int   g_dst[EN_CAP];
__device__ int   g_csr_src[EN_CAP];
__device__ int   g_deg[N_CAP];
__device__ int   g_inc[N_CAP];
__device__ int   g_off[N_CAP + 1];
__device__ int   g_cursor[N_CAP];
__device__ int   g_bsum[256];
__device__ int   g_boff[256];
__device__ float g_psum[64 * 8];
__device__ float g_pcnt[64];
__device__ int   g_is64;

// ---------------- helpers ----------------------------------------------------
__device__ __forceinline__ float lrelu(float x) { return x > 0.f ? x : NEG_SLOPE * x; }

// ---------------- index-width detection --------------------------------------
__global__ void k_detect(const unsigned* __restrict__ w, int pairs) {
    __shared__ int any;
    if (threadIdx.x == 0) any = 0;
    __syncthreads();
    int lim = pairs < 4096 ? pairs : 4096;
    int local = 0;
    for (int i = threadIdx.x; i < lim; i += blockDim.x)
        if (w[2 * i + 1] != 0u) local = 1;
    if (local) atomicExch(&any, 1);
    __syncthreads();
    if (threadIdx.x == 0) g_is64 = (any == 0) ? 1 : 0;
}

// ---------------- zero transient state ---------------------------------------
__global__ void k_zero(int N) {
    int i = blockIdx.x * blockDim.x + threadIdx.x;
    if (i < N) { g_deg[i] = 0; g_cursor[i] = 0; }
    if (i < 512) g_psum[i] = 0.f;
    if (i < 64)  g_pcnt[i] = 0.f;
}

// ---------------- decode edges + dst histogram --------------------------------
__global__ void k_hist(const void* __restrict__ ei, int E, int N) {
    int i = blockIdx.x * blockDim.x + threadIdx.x;
    int EN = E + N;
    if (i >= EN) return;
    int s, d;
    if (i < E) {
        if (g_is64) {
            const long long* p = (const long long*)ei;
            s = (int)p[i]; d = (int)p[E + i];
        } else {
            const int* p = (const int*)ei;
            s = p[i]; d = p[E + i];
        }
    } else {             // self-loops appended (PyG GATConv behavior)
        s = d = i - E;
    }
    g_src[i] = s;
    g_dst[i] = d;
    atomicAdd(&g_deg[d], 1);
}

// ---------------- 3-phase exclusive scan of g_deg -> g_off --------------------
__global__ __launch_bounds__(SCAN_CHUNK) void k_scanA(int N) {
    __shared__ int sh[SCAN_CHUNK];
    int i = blockIdx.x * SCAN_CHUNK + threadIdx.x;
    int v = (i < N) ? g_deg[i] : 0;
    sh[threadIdx.x] = v;
    __syncthreads();
    for (int off = 1; off < SCAN_CHUNK; off <<= 1) {
        int t = (threadIdx.x >= off) ? sh[threadIdx.x - off] : 0;
        __syncthreads();
        sh[threadIdx.x] += t;
        __syncthreads();
    }
    if (i < N) g_inc[i] = sh[threadIdx.x];
    if (threadIdx.x == SCAN_CHUNK - 1) g_bsum[blockIdx.x] = sh[SCAN_CHUNK - 1];
}

__global__ __launch_bounds__(256) void k_scanB(int NB) {
    __shared__ int sh[256];
    int t = threadIdx.x;
    int v = (t < NB) ? g_bsum[t] : 0;
    sh[t] = v;
    __syncthreads();
    for (int off = 1; off < 256; off <<= 1) {
        int tv = (t >= off) ? sh[t - off] : 0;
        __syncthreads();
        sh[t] += tv;
        __syncthreads();
    }
    if (t < NB) g_boff[t] = sh[t] - v;   // exclusive
}

__global__ void k_scanC(int N) {
    int i = blockIdx.x * blockDim.x + threadIdx.x;
    if (i >= N) return;
    int b = i / SCAN_CHUNK;
    int inc = g_inc[i] + g_boff[b];
    g_off[i] = inc - g_deg[i];
    if (i == N - 1) g_off[N] = inc;
}

// ---------------- scatter edges into CSR order --------------------------------
__global__ void k_csr_scatter(int EN) {
    int i = blockIdx.x * blockDim.x + threadIdx.x;
    if (i >= EN) return;
    int d = g_dst[i];
    int pos = g_off[d] + atomicAdd(&g_cursor[d], 1);
    g_csr_src[pos] = g_src[i];
}

// ---------------- GEMM + fused attention-logit epilogue (round-9 exact) ------
template<int K, int M, int ROWS>
__global__ __launch_bounds__(256) void k_gemm(
    const float* __restrict__ in_ext, int use_int,
    const float* __restrict__ W, const float* __restrict__ bias,
    const float* __restrict__ a_src, const float* __restrict__ a_dst, int N)
{
    constexpr int CG  = M / 4;
    constexpr int RG  = 256 / CG;
    constexpr int RPT = ROWS / RG;
    constexpr int OC  = M / HEADS;
    constexpr int RED = (OC >= 4) ? OC / 4 : 1;
    constexpr int KP  = (K == 128) ? K : (K + 1);
    __shared__ float sW[K * M];
    __shared__ float sIn[ROWS * KP];

    const float* in = use_int ? g_o : in_ext;
    int r0 = blockIdx.x * ROWS;

    for (int i = threadIdx.x; i < K * M; i += 256) sW[i] = W[i];
    for (int i = threadIdx.x; i < ROWS * K; i += 256) {
        int r = i / K, k = i - r * K;
        int gr = r0 + r;
        float v = 0.f;
        if (gr < N) {
            v = in[gr * K + k];
            if (bias) { v += bias[k]; v = fmaxf(v, 0.f); }
        }
        sIn[r * KP + k] = v;
    }
    __syncthreads();

    int cg = threadIdx.x % CG;
    int rg = threadIdx.x / CG;
    float acc[RPT][4];
#pragma unroll
    for (int i = 0; i < RPT; i++)
        acc[i][0] = acc[i][1] = acc[i][2] = acc[i][3] = 0.f;

#pragma unroll 8
    for (int k = 0; k < K; k++) {
        float w0 = sW[k * M + cg * 4 + 0];
        float w1 = sW[k * M + cg * 4 + 1];
        float w2 = sW[k * M + cg * 4 + 2];
        float w3 = sW[k * M + cg * 4 + 3];
#pragma unroll
        for (int i = 0; i < RPT; i++) {
            float a = sIn[(rg * RPT + i) * KP + k];
            acc[i][0] += a * w0; acc[i][1] += a * w1;
            acc[i][2] += a * w2; acc[i][3] += a * w3;
        }
    }

    float4 asv = *(const float4*)&a_src[cg * 4];
    float4 adv = *(const float4*)&a_dst[cg * 4];

#pragma unroll
    for (int i = 0; i < RPT; i++) {
        int gr = r0 + rg * RPT + i;
        bool ok = (gr < N);
        if (ok) {
            float4 v = make_float4(acc[i][0], acc[i][1], acc[i][2], acc[i][3]);
            *(float4*)&g_h[gr * M + cg * 4] = v;
        }
        if constexpr (OC >= 4) {
            float vs = acc[i][0]*asv.x + acc[i][1]*asv.y + acc[i][2]*asv.z + acc[i][3]*asv.w;
            float vd = acc[i][0]*adv.x + acc[i][1]*adv.y + acc[i][2]*adv.z + acc[i][3]*adv.w;
#pragma unroll
            for (int o = 1; o < RED; o <<= 1) {
                vs += __shfl_xor_sync(0xffffffffu, vs, o, 32);
                vd += __shfl_xor_sync(0xffffffffu, vd, o, 32);
            }
            if (ok && (cg % RED) == 0) {
                int head = cg / RED;
                g_als[gr * HEADS + head] = vs;
                g_ald[gr * HEADS + head] = vd;
            }
        } else {
            float vs0 = acc[i][0]*asv.x + acc[i][1]*asv.y;
            float vd0 = acc[i][0]*adv.x + acc[i][1]*adv.y;
            float vs1 = acc[i][2]*asv.z + acc[i][3]*asv.w;
            float vd1 = acc[i][2]*adv.z + acc[i][3]*adv.w;
            if (ok) {
                g_als[gr * HEADS + cg * 2 + 0] = vs0;
                g_ald[gr * HEADS + cg * 2 + 0] = vd0;
                g_als[gr * HEADS + cg * 2 + 1] = vs1;
                g_ald[gr * HEADS + cg * 2 + 1] = vd1;
            }
        }
    }
}

// ---------------- fused softmax + aggregation, layer 1 (round-9 exact) --------
// reads g_h/g_als/g_ald, writes g_o — disjoint buffers, no race.
template<int OC>
__global__ __launch_bounds__(256) void k_agg(int N) {
    constexpr int F   = HEADS * OC;
    constexpr int V   = 4;
    constexpr int TPN = F / V;
    constexpr int LPH = OC / V;
    constexpr int NPB = 256 / TPN;
    int node = blockIdx.x * NPB + threadIdx.x / TPN;
    if (node >= N) node = N - 1;
    int t    = threadIdx.x % TPN;
    int head = t / LPH;

    int beg = g_off[node], end = g_off[node + 1];
    float ald_d = g_ald[node * HEADS + head];

    float acc[V];
#pragma unroll
    for (int v = 0; v < V; v++) acc[v] = 0.f;
    float ssum = 0.f;

    int p = beg;
    for (; p + 8 <= end; p += 8) {
        int ss[8];
#pragma unroll
        for (int j = 0; j < 8; j++) ss[j] = g_csr_src[p + j];
        float al[8];
#pragma unroll
        for (int j = 0; j < 8; j++) al[j] = g_als[ss[j] * HEADS + head];
#pragma unroll
        for (int j = 0; j < 8; j++) {
            float ex = __expf(lrelu(al[j] + ald_d));
            ssum += ex;
            float4 hv = *(const float4*)&g_h[ss[j] * F + t * V];
            acc[0] += ex * hv.x; acc[1] += ex * hv.y;
            acc[2] += ex * hv.z; acc[3] += ex * hv.w;
        }
    }
    for (; p < end; p++) {
        int s = g_csr_src[p];
        float ex = __expf(lrelu(g_als[s * HEADS + head] + ald_d));
        ssum += ex;
        float4 hv = *(const float4*)&g_h[s * F + t * V];
        acc[0] += ex * hv.x; acc[1] += ex * hv.y;
        acc[2] += ex * hv.z; acc[3] += ex * hv.w;
    }

    float inv = 1.f / (ssum + 1e-16f);
    *(float4*)&g_o[node * F + t * V] =
        make_float4(acc[0] * inv, acc[1] * inv, acc[2] * inv, acc[3] * inv);
}

// ---------------- agg layer 2 (F=32) + FUSED GEMM3 + logits3 epilogue ---------
// READS:  g_h (h2), g_als/g_ald (logits2)
// WRITES: g_o (h3, [N,16]), g_als2/g_ald2 (logits3)  — disjoint, race-free.
__global__ __launch_bounds__(256) void k_agg8_g3(
    const float* __restrict__ b2, const float* __restrict__ W3,
    const float* __restrict__ as3, const float* __restrict__ ad3, int N) {
    constexpr int F   = 32;
    constexpr int V   = 4;
    constexpr int TPN = 8;
    constexpr int NPB = 32;
    int node = blockIdx.x * NPB + threadIdx.x / TPN;
    if (node >= N) node = N - 1;       // clamp: duplicate compute, idempotent stores
    int t    = threadIdx.x % TPN;
    int head = t / 2;                  // LPH = 2 (OC=8, V=4)
    int lane = threadIdx.x % 32;

    int beg = g_off[node], end = g_off[node + 1];
    float ald_d = g_ald[node * HEADS + head];

    float acc[V] = {0.f, 0.f, 0.f, 0.f};
    float ssum = 0.f;

    int p = beg;
    for (; p + 8 <= end; p += 8) {
        int ss[8];
#pragma unroll
        for (int j = 0; j < 8; j++) ss[j] = g_csr_src[p + j];
        float al[8];
#pragma unroll
        for (int j = 0; j < 8; j++) al[j] = g_als[ss[j] * HEADS + head];
#pragma unroll
        for (int j = 0; j < 8; j++) {
            float ex = __expf(lrelu(al[j] + ald_d));
            ssum += ex;
            float4 hv = *(const float4*)&g_h[ss[j] * F + t * V];
            acc[0] += ex * hv.x; acc[1] += ex * hv.y;
            acc[2] += ex * hv.z; acc[3] += ex * hv.w;
        }
    }
    for (; p < end; p++) {
        int s = g_csr_src[p];
        float ex = __expf(lrelu(g_als[s * HEADS + head] + ald_d));
        ssum += ex;
        float4 hv = *(const float4*)&g_h[s * F + t * V];
        acc[0] += ex * hv.x; acc[1] += ex * hv.y;
        acc[2] += ex * hv.z; acc[3] += ex * hv.w;
    }

    float inv = 1.f / (ssum + 1e-16f);
    float4 bb = *(const float4*)&b2[t * 4];
    float v0 = fmaxf(acc[0] * inv + bb.x, 0.f);
    float v1 = fmaxf(acc[1] * inv + bb.y, 0.f);
    float v2 = fmaxf(acc[2] * inv + bb.z, 0.f);
    float v3 = fmaxf(acc[3] * inv + bb.w, 0.f);

    // h3 cols 2t, 2t+1 = sum_j v_all[j] * W3[j][2t..2t+1]
    // full-mask shfl: all 32 lanes execute the identical static sequence
    int gbase = lane & ~7;             // this node's lane-group base
    float h0 = 0.f, h1 = 0.f;
#pragma unroll
    for (int j = 0; j < 32; j++) {
        int src = gbase + (j >> 2);
        float vj;
        switch (j & 3) {
            case 0: vj = __shfl_sync(0xffffffffu, v0, src, 32); break;
            case 1: vj = __shfl_sync(0xffffffffu, v1, src, 32); break;
            case 2: vj = __shfl_sync(0xffffffffu, v2, src, 32); break;
            default:vj = __shfl_sync(0xffffffffu, v3, src, 32); break;
        }
        float2 w = *(const float2*)&W3[j * 16 + t * 2];
        h0 += vj * w.x; h1 += vj * w.y;
    }

    *(float2*)&g_o[node * 16 + t * 2] = make_float2(h0, h1);

    // logits3: OC=4; this thread's 2 cols are in head t/2; combine with partner
    float2 asw = *(const float2*)&as3[t * 2];
    float2 adw = *(const float2*)&ad3[t * 2];
    float ps = h0 * asw.x + h1 * asw.y;
    float pd = h0 * adw.x + h1 * adw.y;
    ps += __shfl_xor_sync(0xffffffffu, ps, 1, 32);
    pd += __shfl_xor_sync(0xffffffffu, pd, 1, 32);
    if ((t & 1) == 0) {
        g_als2[node * HEADS + t / 2] = ps;
        g_ald2[node * HEADS + t / 2] = pd;
    }
}

// ---------------- agg layer 3 (F=16) + FUSED GEMM4 + logits4 epilogue ---------
// READS:  g_o (h3, [N,16]), g_als2/g_ald2 (logits3)
// WRITES: g_h (h4, [N,8]), g_als/g_ald (logits4)  — disjoint, race-free.
__global__ __launch_bounds__(256) void k_agg4_g4(
    const float* __restrict__ b3, const float* __restrict__ W4,
    const float* __restrict__ as4, const float* __restrict__ ad4, int N) {
    constexpr int F   = 16;
    constexpr int V   = 4;
    constexpr int TPN = 4;
    constexpr int NPB = 64;
    int node = blockIdx.x * NPB + threadIdx.x / TPN;
    if (node >= N) node = N - 1;       // clamp: idempotent stores
    int t    = threadIdx.x % TPN;
    int head = t;                      // LPH = 1 (OC=4, V=4)
    int lane = threadIdx.x % 32;

    int beg = g_off[node], end = g_off[node + 1];
    float ald_d = g_ald2[node * HEADS + head];

    float acc[V] = {0.f, 0.f, 0.f, 0.f};
    float ssum = 0.f;

    int p = beg;
    for (; p + 8 <= end; p += 8) {
        int ss[8];
#pragma unroll
        for (int j = 0; j < 8; j++) ss[j] = g_csr_src[p + j];
        float al[8];
#pragma unroll
        for (int j = 0; j < 8; j++) al[j] = g_als2[ss[j] * HEADS + head];
#pragma unroll
        for (int j = 0; j < 8; j++) {
            float ex = __expf(lrelu(al[j] + ald_d));
            ssum += ex;
            float4 hv = *(const float4*)&g_o[ss[j] * F + t * V];
            acc[0] += ex * hv.x; acc[1] += ex * hv.y;
            acc[2] += ex * hv.z; acc[3] += ex * hv.w;
        }
    }
    for (; p < end; p++) {
        int s = g_csr_src[p];
        float ex = __expf(lrelu(g_als2[s * HEADS + head] + ald_d));
        ssum += ex;
        float4 hv = *(const float4*)&g_o[s * F + t * V];
        acc[0] += ex * hv.x; acc[1] += ex * hv.y;
        acc[2] += ex * hv.z; acc[3] += ex * hv.w;
    }

    float inv = 1.f / (ssum + 1e-16f);
    float4 bb = *(const float4*)&b3[t * 4];
    float v0 = fmaxf(acc[0] * inv + bb.x, 0.f);
    float v1 = fmaxf(acc[1] * inv + bb.y, 0.f);
    float v2 = fmaxf(acc[2] * inv + bb.z, 0.f);
    float v3 = fmaxf(acc[3] * inv + bb.w, 0.f);

    int gbase = lane & ~3;
    float h0 = 0.f, h1 = 0.f;
#pragma unroll
    for (int j = 0; j < 16; j++) {
        int src = gbase + (j >> 2);
        float vj;
        switch (j & 3) {
            case 0: vj = __shfl_sync(0xffffffffu, v0, src, 32); break;
            case 1: vj = __shfl_sync(0xffffffffu, v1, src, 32); break;
            case 2: vj = __shfl_sync(0xffffffffu, v2, src, 32); break;
            default:vj = __shfl_sync(0xffffffffu, v3, src, 32); break;
        }
        float2 w = *(const float2*)&W4[j * 8 + t * 2];
        h0 += vj * w.x; h1 += vj * w.y;
    }

    *(float2*)&g_h[node * 8 + t * 2] = make_float2(h0, h1);

    // OC=2: cols 2t,2t+1 == head t — logits fully local
    float2 asw = *(const float2*)&as4[t * 2];
    float2 adw = *(const float2*)&ad4[t * 2];
    g_als[node * HEADS + t] = h0 * asw.x + h1 * asw.y;
    g_ald[node * HEADS + t] = h0 * adw.x + h1 * adw.y;
}

// ---------------- layer-4 agg with FUSED mean-pool epilogue (round-13) --------
// READS: g_h (h4), g_als/g_ald (logits4). WRITES: g_psum/g_pcnt only.
__global__ __launch_bounds__(256) void k_agg_pool(
    const void* __restrict__ batch, const float* __restrict__ b4, int N) {
    constexpr int F   = 8;
    constexpr int V   = 2;
    constexpr int TPN = 4;
    constexpr int NPB = 64;
    int raw  = blockIdx.x * NPB + threadIdx.x / TPN;
    bool valid = (raw < N);
    int node = valid ? raw : N - 1;
    int t    = threadIdx.x % TPN;
    int head = t;

    int beg = g_off[node], end = g_off[node + 1];
    float ald_d = g_ald[node * HEADS + head];

    float acc0 = 0.f, acc1 = 0.f, ssum = 0.f;

    int p = beg;
    for (; p + 8 <= end; p += 8) {
        int ss[8];
#pragma unroll
        for (int j = 0; j < 8; j++) ss[j] = g_csr_src[p + j];
        float al[8];
#pragma unroll
        for (int j = 0; j < 8; j++) al[j] = g_als[ss[j] * HEADS + head];
#pragma unroll
        for (int j = 0; j < 8; j++) {
            float ex = __expf(lrelu(al[j] + ald_d));
            ssum += ex;
            float2 hv = *(const float2*)&g_h[ss[j] * F + t * V];
            acc0 += ex * hv.x; acc1 += ex * hv.y;
        }
    }
    for (; p < end; p++) {
        int s = g_csr_src[p];
        float ex = __expf(lrelu(g_als[s * HEADS + head] + ald_d));
        ssum += ex;
        float2 hv = *(const float2*)&g_h[s * F + t * V];
        acc0 += ex * hv.x; acc1 += ex * hv.y;
    }

    float inv = 1.f / (ssum + 1e-16f);
    float v0 = fmaxf(acc0 * inv + b4[t * V + 0], 0.f);
    float v1 = fmaxf(acc1 * inv + b4[t * V + 1], 0.f);

    if (valid) {
        int g = g_is64 ? (int)((const long long*)batch)[node]
                       : ((const int*)batch)[node];
        atomicAdd(&g_psum[g * F + t * V + 0], v0);
        atomicAdd(&g_psum[g * F + t * V + 1], v1);
        if (t == 0) atomicAdd(&g_pcnt[g], 1.f);
    }
}

// ---------------- fc ----------------------------------------------------------
__global__ void k_fc(const float* __restrict__ Wfc,
                     const float* __restrict__ bfc, float* __restrict__ out) {
    int b = blockIdx.x, o = threadIdx.x;  // grid 64, block 32
    float c = fmaxf(g_pcnt[b], 1.f);
    float acc = bfc[o];
#pragma unroll
    for (int j = 0; j < 8; j++)
        acc += (g_psum[b * 8 + j] / c) * Wfc[j * 32 + o];
    out[b * 32 + o] = acc;
}

// ---------------- launch ------------------------------------------------------
extern "C" void kernel_launch(void* const* d_in, const int* in_sizes, int n_in,
                              void* d_out, int out_size) {
    const float* x    = (const float*)d_in[0];
    const void*  ei   = d_in[1];
    const void*  batch= d_in[2];
    const float* W1  = (const float*)d_in[3];
    const float* as1 = (const float*)d_in[4];
    const float* ad1 = (const float*)d_in[5];
    const float* b1  = (const float*)d_in[6];
    const float* W2  = (const float*)d_in[7];
    const float* as2 = (const float*)d_in[8];
    const float* ad2 = (const float*)d_in[9];
    const float* b2  = (const float*)d_in[10];
    const float* W3  = (const float*)d_in[11];
    const float* as3 = (const float*)d_in[12];
    const float* ad3 = (const float*)d_in[13];
    const float* b3  = (const float*)d_in[14];
    const float* W4  = (const float*)d_in[15];
    const float* as4 = (const float*)d_in[16];
    const float* ad4 = (const float*)d_in[17];
    const float* b4  = (const float*)d_in[18];
    const float* Wfc = (const float*)d_in[19];
    const float* bfc = (const float*)d_in[20];
    float* out = (float*)d_out;

    int N  = in_sizes[0] / 128;
    int E  = in_sizes[1] / 2;
    int EN = E + N;

    int nb = (N + 255) / 256;
    int eb = (EN + 255) / 256;
    int NB = (N + SCAN_CHUNK - 1) / SCAN_CHUNK;

    // Side stream + fork/join events, created once on the FIRST call (the
    // correctness run, which is NOT captured) — nothing created inside the
    // graph, no device memory allocated.
    static cudaStream_t s2 = nullptr;
    static cudaEvent_t evFork = nullptr, evJoin = nullptr;
    if (s2 == nullptr) {
        cudaStreamCreateWithFlags(&s2, cudaStreamNonBlocking);
        cudaEventCreateWithFlags(&evFork, cudaEventDisableTiming);
        cudaEventCreateWithFlags(&evJoin, cudaEventDisableTiming);
    }

    // ---- fork: CSR build on s2, GEMM1 on the main stream, concurrently ----
    cudaEventRecord(evFork, 0);
    cudaStreamWaitEvent(s2, evFork, 0);

    k_detect<<<1, 256, 0, s2>>>((const unsigned*)ei, E);
    k_zero<<<nb, 256, 0, s2>>>(N);
    k_hist<<<eb, 256, 0, s2>>>(ei, E, N);
    k_scanA<<<NB, SCAN_CHUNK, 0, s2>>>(N);
    k_scanB<<<1, 256, 0, s2>>>(NB);
    k_scanC<<<nb, 256, 0, s2>>>(N);
    k_csr_scatter<<<eb, 256, 0, s2>>>(EN);

    // layer-1 GEMM runs concurrently on the main stream (depends only on x/W1)
    k_gemm<128, 64, 32><<<(N + 31) / 32, 256>>>(x, 0, W1, nullptr, as1, ad1, N);

    // ---- join: aggregation needs both the CSR and GEMM1 results ----
    cudaEventRecord(evJoin, s2);
    cudaStreamWaitEvent(0, evJoin, 0);

    // ---- layer 1 (F = 64): agg -> g_o ----
    k_agg<16><<<(N + 15) / 16, 256>>>(N);

    // ---- layer 2: GEMM2 (g_o -> g_h + logits A); agg fuses GEMM3 + logits3 (-> g_o, B) ----
    k_gemm<64, 32, 128><<<(N + 127) / 128, 256>>>(nullptr, 1, W2, b1, as2, ad2, N);
    k_agg8_g3<<<(N + 31) / 32, 256>>>(b2, W3, as3, ad3, N);

    // ---- layer 3 agg fuses GEMM4 + logits4 (B -> A) ----
    k_agg4_g4<<<(N + 63) / 64, 256>>>(b3, W4, as4, ad4, N);

    // ---- layer 4: agg with fused mean-pool (reads A) ----
    k_agg_pool<<<(N + 63) / 64, 256>>>(batch, b4, N);

    // ---- fc ----
    k_fc<<<64, 32>>>(Wfc, bfc, out);
}